// round 16
// baseline (speedup 1.0000x reference)
#include <cuda_runtime.h>
#include <cuda_bf16.h>
#include <cstdint>

// ---------------- problem constants ----------------
#define SEQ   2048
#define EDIM  512
#define HDIM  256
#define TTAGS 32
#define TSTART 30
#define TSTOP  31
#define NEGV  (-10000.0f)

// ---------------- device scratch (no allocs allowed) ----------------
__device__ float g_px[2][SEQ][1024];     // input projections (bias fused), per dir
__device__ float g_h[2][SEQ][HDIM];      // lstm hidden outputs, per dir
__device__ float g_feats[SEQ][TTAGS];    // tag scores
__device__ float g_wtagT[EDIM][TTAGS];   // transposed tag weights
__device__ int   g_bptr[SEQ][TTAGS];     // viterbi backpointers

// ---------------- small helpers ----------------
__device__ __forceinline__ unsigned long long pack2f(float x, float y) {
    unsigned long long r;
    asm("mov.b64 %0, {%1, %2};" : "=l"(r) : "f"(x), "f"(y));
    return r;
}
__device__ __forceinline__ float2 unpack2f(unsigned long long v) {
    float2 r;
    asm("mov.b64 {%0, %1}, %2;" : "=f"(r.x), "=f"(r.y) : "l"(v));
    return r;
}
__device__ __forceinline__ void fma2(unsigned long long& d, unsigned long long a,
                                     unsigned long long b) {
    asm("fma.rn.f32x2 %0, %1, %2, %0;" : "+l"(d) : "l"(a), "l"(b));
}
__device__ __forceinline__ unsigned smem_u32(const void* p) {
    unsigned a;
    asm("{ .reg .u64 t; cvta.to.shared.u64 t, %1; cvt.u32.u64 %0, t; }"
        : "=r"(a) : "l"(p));
    return a;
}
__device__ __forceinline__ void st_cluster_f32(unsigned addr, int rank, float v) {
    unsigned ra;
    asm("mapa.shared::cluster.u32 %0, %1, %2;" : "=r"(ra) : "r"(addr), "r"(rank));
    asm volatile("st.shared::cluster.f32 [%0], %1;" :: "r"(ra), "f"(v) : "memory");
}
__device__ __forceinline__ void cluster_sync_() {
    asm volatile("barrier.cluster.arrive.aligned;" ::: "memory");
    asm volatile("barrier.cluster.wait.aligned;" ::: "memory");
}
__device__ __forceinline__ float sigmoidf_(float x) {
    return 1.0f / (1.0f + __expf(-x));
}

// ============================================================================
// Kernel 1: px GEMM (round-13 winner). 128x128 tile, K-tile 8, 8x8 microtile,
// packed f32x2 accumulation, float4 global loads. grid (16, 8, 2).
// ============================================================================
__global__ __launch_bounds__(256)
void px_gemm(const int* __restrict__ sent, const float* __restrict__ embed,
             const float* __restrict__ w_ih_f, const float* __restrict__ b_f,
             const float* __restrict__ w_ih_b, const float* __restrict__ b_b)
{
    int dir = blockIdx.z;
    const float* W  = dir ? w_ih_b : w_ih_f;
    const float* Bv = dir ? b_b    : b_f;
    int t0 = blockIdx.x * 128;
    int r0 = blockIdx.y * 128;

    __shared__ __align__(16) float As[8][128];
    __shared__ __align__(16) float Bs[8][132];
    __shared__ int ssent[128];

    int tid = threadIdx.x;
    if (tid < 128) ssent[tid] = sent[t0 + tid];
    __syncthreads();

    int tx = tid & 15, ty = tid >> 4;
    int lt = tid >> 1;
    int lh = tid & 1;

    unsigned long long acc2[8][4];
#pragma unroll
    for (int i = 0; i < 8; i++)
#pragma unroll
        for (int j = 0; j < 4; j++) acc2[i][j] = 0ull;

    const size_t erow = (size_t)ssent[lt] * EDIM;
    const size_t wrow = (size_t)(r0 + lt) * EDIM;

    for (int k0 = 0; k0 < EDIM; k0 += 8) {
        float4 av = *(const float4*)&embed[erow + k0 + lh * 4];
        float4 bw = *(const float4*)&W[wrow + k0 + lh * 4];
        As[lh * 4 + 0][lt] = av.x;
        As[lh * 4 + 1][lt] = av.y;
        As[lh * 4 + 2][lt] = av.z;
        As[lh * 4 + 3][lt] = av.w;
        Bs[lh * 4 + 0][lt] = bw.x;
        Bs[lh * 4 + 1][lt] = bw.y;
        Bs[lh * 4 + 2][lt] = bw.z;
        Bs[lh * 4 + 3][lt] = bw.w;
        __syncthreads();

#pragma unroll
        for (int kk = 0; kk < 8; kk++) {
            float4 a0 = *(const float4*)&As[kk][ty * 8];
            float4 a1 = *(const float4*)&As[kk][ty * 8 + 4];
            ulonglong2 bl0 = *(const ulonglong2*)&Bs[kk][tx * 8];
            ulonglong2 bl1 = *(const ulonglong2*)&Bs[kk][tx * 8 + 4];
            unsigned long long b2[4] = { bl0.x, bl0.y, bl1.x, bl1.y };
            float a[8] = { a0.x, a0.y, a0.z, a0.w, a1.x, a1.y, a1.z, a1.w };
#pragma unroll
            for (int i = 0; i < 8; i++) {
                unsigned long long ad = pack2f(a[i], a[i]);
#pragma unroll
                for (int j = 0; j < 4; j++) fma2(acc2[i][j], ad, b2[j]);
            }
        }
        __syncthreads();
    }

    float bias[8];
#pragma unroll
    for (int j = 0; j < 8; j++) bias[j] = Bv[r0 + tx * 8 + j];
#pragma unroll
    for (int i = 0; i < 8; i++) {
        int t = t0 + ty * 8 + i;
        float o[8];
#pragma unroll
        for (int j = 0; j < 4; j++) {
            float2 v = unpack2f(acc2[i][j]);
            o[2 * j]     = v.x + bias[2 * j];
            o[2 * j + 1] = v.y + bias[2 * j + 1];
        }
        float* dst = &g_px[dir][t][r0 + tx * 8];
        *(float4*)dst       = make_float4(o[0], o[1], o[2], o[3]);
        *(float4*)(dst + 4) = make_float4(o[4], o[5], o[6], o[7]);
    }
}

// ============================================================================
// Kernel 2: transpose w_tag [32,512] -> g_wtagT [512,32]
// ============================================================================
__global__ void wtagT_kernel(const float* __restrict__ w_tag)
{
    int idx = blockIdx.x * blockDim.x + threadIdx.x;
    if (idx < TTAGS * EDIM) {
        int tag = idx >> 9;
        int e   = idx & 511;
        g_wtagT[e][tag] = w_tag[idx];
    }
}

// ============================================================================
// Kernel 3: BiLSTM recurrence. EXACT 2875us best (round-9 winner). FROZEN.
// ============================================================================
__global__ void __cluster_dims__(8, 1, 1) __launch_bounds__(512, 1)
lstm_kernel(const float* __restrict__ w_hh_f, const float* __restrict__ w_hh_b,
            const float* __restrict__ h0, const float* __restrict__ c0)
{
    int dir  = blockIdx.x >> 3;
    int rank = blockIdx.x & 7;
    const float* W  = dir ? w_hh_b : w_hh_f;
    const float* px = &g_px[dir][0][0];
    float* hout     = &g_h[dir][0][0];

    int tid  = threadIdx.x;
    int ks   = tid >> 7;        // 0..3  (k slice of 64)
    int r    = tid & 127;       // 0..127 (gate row within CTA)
    int grow = (r >> 5) * 256 + rank * 32 + (r & 31);   // gate row in [0,1024)

    __shared__ __align__(16) float h_sh[2][HDIM];
    __shared__ float red_sh[4][128];

    // load weight slice into registers, packed as f32x2
    unsigned long long w2[32];
    {
        const float2* wp = (const float2*)(W + (size_t)grow * HDIM + ks * 64);
#pragma unroll
        for (int i = 0; i < 32; i++) {
            float2 v = wp[i];
            w2[i] = pack2f(v.x, v.y);
        }
    }

    // initial state
    if (tid < HDIM) h_sh[0][tid] = h0[dir * HDIM + tid];
    float c = 0.0f;
    if (tid < 32) c = c0[dir * HDIM + rank * 32 + tid];

    // warp0: prefetch px for step 0 (the 4 gate rows of unit `tid`)
    float px4_0 = 0.f, px4_1 = 0.f, px4_2 = 0.f, px4_3 = 0.f;
    if (tid < 32) {
        int t0i = dir ? (SEQ - 1) : 0;
        const float* p0 = &px[(size_t)t0i * 1024 + rank * 32 + tid];
        px4_0 = __ldg(p0);
        px4_1 = __ldg(p0 + 256);
        px4_2 = __ldg(p0 + 512);
        px4_3 = __ldg(p0 + 768);
    }

    __syncthreads();
    cluster_sync_();

    int p = 0;
    for (int step = 0; step < SEQ; ++step) {
        int t = dir ? (SEQ - 1 - step) : step;

        // matvec partial: 64 MACs via 32 packed FFMA2
        unsigned long long a0 = 0ull, a1 = 0ull;
        const ulonglong2* hp = (const ulonglong2*)&h_sh[p][ks * 64];
#pragma unroll
        for (int i = 0; i < 16; i += 2) {
            ulonglong2 u = hp[i];
            ulonglong2 v = hp[i + 1];
            fma2(a0, w2[2 * i], u.x);
            fma2(a1, w2[2 * i + 1], u.y);
            fma2(a0, w2[2 * i + 2], v.x);
            fma2(a1, w2[2 * i + 3], v.y);
        }
        float2 f0 = unpack2f(a0), f1 = unpack2f(a1);
        red_sh[ks][r] = (f0.x + f0.y) + (f1.x + f1.y);
        __syncthreads();

        // warp0: reduce all 4 gates + activations + cell/hidden + broadcast
        if (tid < 32) {
            float v0 = red_sh[0][tid]      + red_sh[1][tid]      +
                       red_sh[2][tid]      + red_sh[3][tid]      + px4_0;
            float v1 = red_sh[0][32 + tid] + red_sh[1][32 + tid] +
                       red_sh[2][32 + tid] + red_sh[3][32 + tid] + px4_1;
            float v2 = red_sh[0][64 + tid] + red_sh[1][64 + tid] +
                       red_sh[2][64 + tid] + red_sh[3][64 + tid] + px4_2;
            float v3 = red_sh[0][96 + tid] + red_sh[1][96 + tid] +
                       red_sh[2][96 + tid] + red_sh[3][96 + tid] + px4_3;
            float ai = sigmoidf_(v0);
            float af = sigmoidf_(v1);
            float ag = tanhf(v2);
            float ao = sigmoidf_(v3);
            c = af * c + ai * ag;
            float hn = ao * tanhf(c);
            hout[(size_t)t * HDIM + rank * 32 + tid] = hn;
            unsigned laddr = smem_u32(&h_sh[p ^ 1][rank * 32 + tid]);
#pragma unroll
            for (int cc = 0; cc < 8; cc++) st_cluster_f32(laddr, cc, hn);

            // prefetch px for next step; LDG latency hides under cluster.sync
            if (step + 1 < SEQ) {
                int tn = dir ? (SEQ - 2 - step) : (step + 1);
                const float* p0 = &px[(size_t)tn * 1024 + rank * 32 + tid];
                px4_0 = __ldg(p0);
                px4_1 = __ldg(p0 + 256);
                px4_2 = __ldg(p0 + 512);
                px4_3 = __ldg(p0 + 768);
            }
        }
        cluster_sync_();
        p ^= 1;
    }
}

// ============================================================================
// Kernel 4: feats[t][tag] = [h_f(t) | h_b(t)] . w_tag[tag] + b_tag[tag]
// ============================================================================
__global__ __launch_bounds__(128)
void proj_kernel(const float* __restrict__ b_tag)
{
    int t = blockIdx.x;
    __shared__ float hs[2 * HDIM];
    __shared__ float red[4][TTAGS];
    int tid = threadIdx.x;
    for (int i = tid; i < HDIM; i += 128) {
        hs[i]        = g_h[0][t][i];
        hs[HDIM + i] = g_h[1][t][i];
    }
    __syncthreads();
    int tag = tid & 31, part = tid >> 5;
    float s = 0.0f;
    const float* hv = hs + part * 128;
    const float* wT = &g_wtagT[part * 128][tag];
#pragma unroll 8
    for (int j = 0; j < 128; j++) s += hv[j] * wT[j * TTAGS];
    red[part][tag] = s;
    __syncthreads();
    if (tid < TTAGS)
        g_feats[t][tid] = red[0][tid] + red[1][tid] + red[2][tid] + red[3][tid] +
                          b_tag[tid];
}

// ============================================================================
// Kernel 5: Viterbi, 4-warp forward, PLAIN __syncthreads (hang-proof: all
// 128 threads pass both barriers unconditionally; no named-barrier
// arrive/sync split, no divergent barrier ops).
// Warp w handles predecessors j in [8w, 8w+8) for all 32 dest tags
// (lane = dest tag): broadcast LDS of fv + 8 FADD + fmaxf tree +
// equality-mask/ffs first-max index (== jnp.argmax semantics; max is exact
// so the value set is bitwise identical to the single-warp version).
// Warp 0 then combines the 4 partials with strict > (ascending group order
// preserves lowest-index ties), adds feat, stores bptr, publishes fv
// (double-buffered SMEM). Terminal + backtrack on warp 0 only.
// ============================================================================
__global__ __launch_bounds__(128)
void viterbi_kernel(const float* __restrict__ trans, float* __restrict__ out,
                    int out_size)
{
    const unsigned FULL = 0xffffffffu;
    int tid = threadIdx.x;
    int w = tid >> 5, l = tid & 31;

    __shared__ float fv_sh[2][TTAGS];
    __shared__ float red_v[4][33];
    __shared__ int   red_i[4][33];

    // tr8[jj] = trans[l][8w + jj]
    float tr8[8];
#pragma unroll
    for (int jj = 0; jj < 8; jj++) tr8[jj] = trans[l * TTAGS + 8 * w + jj];

    float fv = (l == TSTART) ? 0.0f : NEGV;   // warp0 keeps the live fv
    float feat = 0.0f;
    if (tid < 32) {
        fv_sh[0][l] = fv;
        feat = g_feats[0][l];
    }
    __syncthreads();

    int p = 0;
    for (int t = 0; t < SEQ; t++) {
        int q = p ^ 1;

        // phase 1 (all 4 warps): partial max over this warp's 8 predecessors
        float s0 = fv_sh[p][8 * w + 0] + tr8[0];
        float s1 = fv_sh[p][8 * w + 1] + tr8[1];
        float s2 = fv_sh[p][8 * w + 2] + tr8[2];
        float s3 = fv_sh[p][8 * w + 3] + tr8[3];
        float s4 = fv_sh[p][8 * w + 4] + tr8[4];
        float s5 = fv_sh[p][8 * w + 5] + tr8[5];
        float s6 = fv_sh[p][8 * w + 6] + tr8[6];
        float s7 = fv_sh[p][8 * w + 7] + tr8[7];
        float m = fmaxf(fmaxf(fmaxf(s0, s1), fmaxf(s2, s3)),
                        fmaxf(fmaxf(s4, s5), fmaxf(s6, s7)));
        unsigned mk = ((s0 == m) ? 1u : 0u)   | ((s1 == m) ? 2u : 0u)
                    | ((s2 == m) ? 4u : 0u)   | ((s3 == m) ? 8u : 0u)
                    | ((s4 == m) ? 16u : 0u)  | ((s5 == m) ? 32u : 0u)
                    | ((s6 == m) ? 64u : 0u)  | ((s7 == m) ? 128u : 0u);
        red_v[w][l] = m;
        red_i[w][l] = 8 * w + (__ffs(mk) - 1);
        __syncthreads();

        // phase 2 (warp 0): combine groups; ascending j + strict > keeps
        // the first (lowest-index) max, matching jnp.argmax
        if (tid < 32) {
            float v0 = red_v[0][l], v1 = red_v[1][l];
            float v2 = red_v[2][l], v3 = red_v[3][l];
            int  i0 = red_i[0][l], i1 = red_i[1][l];
            int  i2 = red_i[2][l], i3 = red_i[3][l];
            float bv = v0; int bi = i0;
            if (v1 > bv) { bv = v1; bi = i1; }
            if (v2 > bv) { bv = v2; bi = i2; }
            if (v3 > bv) { bv = v3; bi = i3; }
            g_bptr[t][l] = bi;
            fv = bv + feat;
            fv_sh[q][l] = fv;
            if (t + 1 < SEQ) feat = g_feats[t + 1][l];
        }
        __syncthreads();
        p = q;
    }

    // terminal + backtrack: warp 0 only
    if (tid < 32) {
        float term = fv + trans[TSTOP * TTAGS + l];
        float bv = term; int bi = l;
#pragma unroll
        for (int off = 16; off >= 1; off >>= 1) {
            float ov = __shfl_xor_sync(FULL, bv, off);
            int   oi = __shfl_xor_sync(FULL, bi, off);
            if (ov > bv || (ov == bv && oi < bi)) { bv = ov; bi = oi; }
        }
        if (l == 0 && out_size > 0) out[0] = bv;

        int tag = bi;
        for (int t0 = SEQ - 16; t0 >= 0; t0 -= 16) {
            int rows[16];
#pragma unroll
            for (int k = 0; k < 16; k++) rows[k] = g_bptr[t0 + k][l];
#pragma unroll
            for (int k = 15; k >= 0; k--) {
                int t = t0 + k;
                if (l == 0 && 1 + t < out_size) out[1 + t] = (float)tag;
                tag = __shfl_sync(FULL, rows[k], tag);
            }
        }
    }
}

// ============================================================================
// launcher
// ============================================================================
extern "C" void kernel_launch(void* const* d_in, const int* in_sizes, int n_in,
                              void* d_out, int out_size)
{
    const int*   sent    = (const int*)d_in[0];
    const float* embed   = (const float*)d_in[1];
    const float* w_ih_f  = (const float*)d_in[2];
    const float* w_hh_f  = (const float*)d_in[3];
    const float* b_f     = (const float*)d_in[4];
    const float* w_ih_b  = (const float*)d_in[5];
    const float* w_hh_b  = (const float*)d_in[6];
    const float* b_b     = (const float*)d_in[7];
    const float* w_tag   = (const float*)d_in[8];
    const float* b_tag   = (const float*)d_in[9];
    const float* trans   = (const float*)d_in[10];
    const float* h0      = (const float*)d_in[11];
    const float* c0      = (const float*)d_in[12];
    float* out = (float*)d_out;

    dim3 g1(SEQ / 128, 1024 / 128, 2);
    px_gemm<<<g1, 256>>>(sent, embed, w_ih_f, b_f, w_ih_b, b_b);
    wtagT_kernel<<<(TTAGS * EDIM + 511) / 512, 512>>>(w_tag);
    lstm_kernel<<<16, 512>>>(w_hh_f, w_hh_b, h0, c0);
    proj_kernel<<<SEQ, 128>>>(b_tag);
    viterbi_kernel<<<1, 128>>>(trans, out, out_size);
}